// round 7
// baseline (speedup 1.0000x reference)
#include <cuda_runtime.h>
#include <cuda_bf16.h>
#include <math.h>
#include <stdint.h>

#define Bb 8
#define Nn 4096
#define Dd 128
#define TKr 64
#define KTILES (Nn/TKr)     // 64

// ---------------- device scratch (no allocs allowed) ----------------
// bf16 hi/lo row-major [B*N][128]
__device__ __align__(16) __nv_bfloat16 g_Qhi[Bb*Nn*Dd];
__device__ __align__(16) __nv_bfloat16 g_Qlo[Bb*Nn*Dd];
__device__ __align__(16) __nv_bfloat16 g_Khi[Bb*Nn*Dd];
__device__ __align__(16) __nv_bfloat16 g_Klo[Bb*Nn*Dd];
__device__ __align__(16) __nv_bfloat16 g_Vhi[Bb*Nn*Dd];
__device__ __align__(16) __nv_bfloat16 g_Vlo[Bb*Nn*Dd];

__device__ __forceinline__ uint32_t smem_u32(const void* p) {
    uint32_t a;
    asm("{ .reg .u64 t; cvta.to.shared.u64 t, %1; cvt.u32.u64 %0, t; }" : "=r"(a) : "l"(p));
    return a;
}

#define LDSM4(r, addr) \
    asm volatile("ldmatrix.sync.aligned.m8n8.x4.shared.b16 {%0,%1,%2,%3}, [%4];" \
        : "=r"((r)[0]), "=r"((r)[1]), "=r"((r)[2]), "=r"((r)[3]) : "r"(addr))
#define LDSM4T(r, addr) \
    asm volatile("ldmatrix.sync.aligned.m8n8.x4.trans.shared.b16 {%0,%1,%2,%3}, [%4];" \
        : "=r"((r)[0]), "=r"((r)[1]), "=r"((r)[2]), "=r"((r)[3]) : "r"(addr))
#define MMA16816(d, a, b0, b1) \
    asm volatile("mma.sync.aligned.m16n8k16.row.col.f32.bf16.bf16.f32 " \
        "{%0,%1,%2,%3}, {%4,%5,%6,%7}, {%8,%9}, {%0,%1,%2,%3};" \
        : "+f"((d)[0]), "+f"((d)[1]), "+f"((d)[2]), "+f"((d)[3]) \
        : "r"((a)[0]), "r"((a)[1]), "r"((a)[2]), "r"((a)[3]), "r"(b0), "r"(b1))
#define CP_ASYNC16(sdst, gsrc) \
    asm volatile("cp.async.cg.shared.global [%0], [%1], 16;" :: "r"(sdst), "l"(gsrc))
#define CP_COMMIT() asm volatile("cp.async.commit_group;" ::: "memory")
#define CP_WAIT1()  asm volatile("cp.async.wait_group 1;" ::: "memory")
#define CP_WAIT0()  asm volatile("cp.async.wait_group 0;" ::: "memory")

// hi/lo split of 2 floats -> two packed bf16x2 words
__device__ __forceinline__ void split2(float f0, float f1, uint32_t& hw, uint32_t& lw) {
    __nv_bfloat162 hh = __floats2bfloat162_rn(f0, f1);
    float r0 = f0 - __bfloat162float(hh.x);
    float r1 = f1 - __bfloat162float(hh.y);
    __nv_bfloat162 ll = __floats2bfloat162_rn(r0, r1);
    hw = *(uint32_t*)&hh;
    lw = *(uint32_t*)&ll;
}

// ---------------------------------------------------------------------------
// Tensorized projection. grid=(256, 3), block=256, smem 128KB.
// Each CTA: 128 rows of X, full 128x128 W. Y = X W^T via 3-pass bf16 hi/lo.
// Emits bf16 hi/lo row-major into g_{Q,K,V}{hi,lo}.
// ---------------------------------------------------------------------------
#define PJ_XHI 0
#define PJ_XLO 32768
#define PJ_WHI 65536
#define PJ_WLO 98304
#define PROJ_SMEM 131072

__global__ __launch_bounds__(256, 1) void proj_kernel(
    const float* __restrict__ X,
    const float* __restrict__ Wq,
    const float* __restrict__ Wk,
    const float* __restrict__ Wv)
{
    extern __shared__ char smem[];
    const uint32_t sb = smem_u32(smem);
    const int tid  = threadIdx.x;
    const int lane = tid & 31;
    const int wid  = tid >> 5;
    const int row0 = blockIdx.x * 128;

    const float* W = (blockIdx.y == 0) ? Wq : (blockIdx.y == 1) ? Wk : Wv;
    __nv_bfloat16* HI = (blockIdx.y == 0) ? g_Qhi : (blockIdx.y == 1) ? g_Khi : g_Vhi;
    __nv_bfloat16* LO = (blockIdx.y == 0) ? g_Qlo : (blockIdx.y == 1) ? g_Klo : g_Vlo;

    // load + split X tile and W into swizzled smem images (2 threads per row)
    {
        const int r = tid >> 1;
        const int h = tid & 1;
        const uint32_t rx = (uint32_t)((r & 7) << 4);
        #pragma unroll
        for (int c4 = 0; c4 < 16; c4++) {
            int col = h*64 + c4*4;
            uint32_t off = (uint32_t)(r*256) + ((((uint32_t)(col >> 3)) << 4) ^ rx) + (uint32_t)((col & 7) << 1);
            float4 v = *(const float4*)(X + (size_t)(row0 + r) * Dd + col);
            uint32_t h0, l0, h1, l1;
            split2(v.x, v.y, h0, l0);
            split2(v.z, v.w, h1, l1);
            *(uint32_t*)(smem + PJ_XHI + off)     = h0;
            *(uint32_t*)(smem + PJ_XHI + off + 4) = h1;
            *(uint32_t*)(smem + PJ_XLO + off)     = l0;
            *(uint32_t*)(smem + PJ_XLO + off + 4) = l1;
            float4 w = *(const float4*)(W + (size_t)r * Dd + col);
            split2(w.x, w.y, h0, l0);
            split2(w.z, w.w, h1, l1);
            *(uint32_t*)(smem + PJ_WHI + off)     = h0;
            *(uint32_t*)(smem + PJ_WHI + off + 4) = h1;
            *(uint32_t*)(smem + PJ_WLO + off)     = l0;
            *(uint32_t*)(smem + PJ_WLO + off + 4) = l1;
        }
    }
    __syncthreads();

    // fragment address components (same layout as attn kernel)
    const int      qrow   = wid*16 + (lane & 15);
    const uint32_t q_base = qrow*256;
    const uint32_t q_xor  = (uint32_t)((qrow & 7) << 4);
    const uint32_t q_ho   = (uint32_t)((lane >> 4) << 4);
    const int      krow   = ((lane >> 4) << 3) + (lane & 7);
    const uint32_t k_base = krow*256;
    const uint32_t k_xor  = (uint32_t)((krow & 7) << 4);
    const uint32_t k_ho   = (uint32_t)(((lane >> 3) & 1) << 4);

    float acc[16][4];
    #pragma unroll
    for (int nb = 0; nb < 16; nb++)
        #pragma unroll
        for (int r = 0; r < 4; r++) acc[nb][r] = 0.0f;

    #pragma unroll
    for (int kk = 0; kk < 8; kk++) {
        uint32_t ah[4], al[4];
        uint32_t qc = ((uint32_t)(kk << 5) + q_ho) ^ q_xor;
        LDSM4(ah, sb + PJ_XHI + q_base + qc);
        LDSM4(al, sb + PJ_XLO + q_base + qc);
        #pragma unroll
        for (int nbp = 0; nbp < 8; nbp++) {
            uint32_t ka = k_base + (uint32_t)(nbp << 12) + ((((uint32_t)(kk << 5)) + k_ho) ^ k_xor);
            uint32_t bh[4], bl[4];
            LDSM4(bh, sb + PJ_WHI + ka);
            MMA16816(acc[2*nbp],   ah, bh[0], bh[1]);
            MMA16816(acc[2*nbp+1], ah, bh[2], bh[3]);
            MMA16816(acc[2*nbp],   al, bh[0], bh[1]);
            MMA16816(acc[2*nbp+1], al, bh[2], bh[3]);
            LDSM4(bl, sb + PJ_WLO + ka);
            MMA16816(acc[2*nbp],   ah, bl[0], bl[1]);
            MMA16816(acc[2*nbp+1], ah, bl[2], bl[3]);
        }
    }

    // epilogue: split fp32 acc -> bf16 hi/lo, write row-major
    const int g  = lane >> 2;
    const int c2 = (lane & 3) << 1;
    const size_t r0 = (size_t)(row0 + wid*16 + g);
    const size_t r1 = r0 + 8;
    #pragma unroll
    for (int nb = 0; nb < 16; nb++) {
        uint32_t hw, lw;
        split2(acc[nb][0], acc[nb][1], hw, lw);
        *(uint32_t*)(HI + r0 * Dd + nb*8 + c2) = hw;
        *(uint32_t*)(LO + r0 * Dd + nb*8 + c2) = lw;
        split2(acc[nb][2], acc[nb][3], hw, lw);
        *(uint32_t*)(HI + r1 * Dd + nb*8 + c2) = hw;
        *(uint32_t*)(LO + r1 * Dd + nb*8 + c2) = lw;
    }
}

// ---------------------------------------------------------------------------
// mma.sync flash attention, cp.async double-buffered, TK=64 per stage.
// grid=(32, 8), block=256. Each warp owns 16 q-rows.
// SMEM: QHI 0..32K | QLO 32K..64K | stage0 64K..128K | stage1 128K..192K
//   within stage: KHI 0 | KLO 16K | VHI 32K | VLO 48K   (64 rows x 256B each)
// ---------------------------------------------------------------------------
#define T_QHI 0
#define T_QLO 32768
#define T_STG 65536
#define STG_STRIDE 65536
#define S_KHI 0
#define S_KLO 16384
#define S_VHI 32768
#define S_VLO 49152
#define ATTN_SMEM 196608

__global__ __launch_bounds__(256, 1) void attn_mma_kernel(float* __restrict__ out)
{
    extern __shared__ char smem[];
    const uint32_t sb = smem_u32(smem);
    const int tid  = threadIdx.x;
    const int lane = tid & 31;
    const int wid  = tid >> 5;
    const int b    = blockIdx.y;
    const int qt   = blockIdx.x;

    // ---- load Q tile (hi/lo), swizzled ----
    {
        const size_t qb = ((size_t)b * Nn + (size_t)qt * 128) * 16;
        const uint4* qh = (const uint4*)g_Qhi;
        const uint4* ql = (const uint4*)g_Qlo;
        #pragma unroll
        for (int i = 0; i < 8; i++) {
            int idx = tid + i * 256;
            int row = idx >> 4, ch = idx & 15;
            uint32_t off = row*256 + (((uint32_t)(ch << 4)) ^ ((uint32_t)((row & 7) << 4)));
            *(uint4*)(smem + T_QHI + off) = qh[qb + idx];
            *(uint4*)(smem + T_QLO + off) = ql[qb + idx];
        }
    }

    // ---- fragment address components ----
    const int      qrow   = wid*16 + (lane & 15);
    const uint32_t q_base = qrow*256;
    const uint32_t q_xor  = (uint32_t)((qrow & 7) << 4);
    const uint32_t q_ho   = (uint32_t)((lane >> 4) << 4);
    const int      krow   = ((lane >> 4) << 3) + (lane & 7);
    const uint32_t k_base = krow*256;
    const uint32_t k_xor  = (uint32_t)((krow & 7) << 4);
    const uint32_t k_ho   = (uint32_t)(((lane >> 3) & 1) << 4);
    const int      vrow   = (((lane >> 3) & 1) << 3) + (lane & 7);
    const uint32_t v_base = vrow*256;
    const uint32_t v_xor  = (uint32_t)((vrow & 7) << 4);
    const uint32_t v_ho   = (uint32_t)((lane >> 4) << 4);

    const uint32_t s_qhi = sb + T_QHI, s_qlo = sb + T_QLO;

    // per-stage prefetch: 16 cp.async per thread (4 matrices x 4 chunks)
    const __nv_bfloat16* kh_g = g_Khi;
    const __nv_bfloat16* kl_g = g_Klo;
    const __nv_bfloat16* vh_g = g_Vhi;
    const __nv_bfloat16* vl_g = g_Vlo;

    auto prefetch = [&](int kt, int stg) {
        const size_t kb = ((size_t)b * Nn + (size_t)kt * TKr) * 16;
        const uint32_t sdst = sb + T_STG + (uint32_t)stg * STG_STRIDE;
        const uint4* kh = (const uint4*)kh_g + kb;
        const uint4* kl = (const uint4*)kl_g + kb;
        const uint4* vh = (const uint4*)vh_g + kb;
        const uint4* vl = (const uint4*)vl_g + kb;
        #pragma unroll
        for (int i = 0; i < 4; i++) {
            int idx = tid + i * 256;                 // 0..1023
            int row = idx >> 4, ch = idx & 15;
            uint32_t off = row*256 + (((uint32_t)(ch << 4)) ^ ((uint32_t)((row & 7) << 4)));
            CP_ASYNC16(sdst + S_KHI + off, (const void*)(kh + idx));
            CP_ASYNC16(sdst + S_KLO + off, (const void*)(kl + idx));
            CP_ASYNC16(sdst + S_VHI + off, (const void*)(vh + idx));
            CP_ASYNC16(sdst + S_VLO + off, (const void*)(vl + idx));
        }
    };

    float O[16][4];
    #pragma unroll
    for (int nb = 0; nb < 16; nb++)
        #pragma unroll
        for (int r = 0; r < 4; r++) O[nb][r] = 0.0f;
    float lsum0 = 0.0f, lsum1 = 0.0f;

    prefetch(0, 0);
    CP_COMMIT();

    for (int kt = 0; kt < KTILES; kt++) {
        __syncthreads();   // all warps done with stage (kt+1)&1 from iteration kt-1
        if (kt + 1 < KTILES) {
            prefetch(kt + 1, (kt + 1) & 1);
            CP_COMMIT();
            CP_WAIT1();    // tile kt landed (this thread)
        } else {
            CP_WAIT0();
        }
        __syncthreads();   // tile kt landed (all threads)

        const uint32_t stg   = sb + T_STG + (uint32_t)(kt & 1) * STG_STRIDE;
        const uint32_t s_khi = stg + S_KHI, s_klo = stg + S_KLO;
        const uint32_t s_vhi = stg + S_VHI, s_vlo = stg + S_VLO;

        // ---- S = Qhi*Khi^T + Qlo*Khi^T + Qhi*Klo^T  (16 x 64) ----
        float S[8][4];
        #pragma unroll
        for (int nb = 0; nb < 8; nb++)
            #pragma unroll
            for (int r = 0; r < 4; r++) S[nb][r] = 0.0f;

        #pragma unroll
        for (int kk = 0; kk < 8; kk++) {
            uint32_t ah[4], al[4];
            uint32_t qc = ((uint32_t)(kk << 5) + q_ho) ^ q_xor;
            LDSM4(ah, s_qhi + q_base + qc);
            LDSM4(al, s_qlo + q_base + qc);
            #pragma unroll
            for (int nbp = 0; nbp < 4; nbp++) {
                uint32_t ka = k_base + (uint32_t)(nbp << 12) + ((((uint32_t)(kk << 5)) + k_ho) ^ k_xor);
                uint32_t bh[4], bl[4];
                LDSM4(bh, s_khi + ka);
                MMA16816(S[2*nbp],   ah, bh[0], bh[1]);
                MMA16816(S[2*nbp+1], ah, bh[2], bh[3]);
                MMA16816(S[2*nbp],   al, bh[0], bh[1]);
                MMA16816(S[2*nbp+1], al, bh[2], bh[3]);
                LDSM4(bl, s_klo + ka);
                MMA16816(S[2*nbp],   ah, bl[0], bl[1]);
                MMA16816(S[2*nbp+1], ah, bl[2], bl[3]);
            }
        }

        // ---- softmax (registers only) + O += Phi*V(hi+lo) + Plo*Vhi ----
        #pragma unroll
        for (int j = 0; j < 4; j++) {
            float pe[8];
            #pragma unroll
            for (int r = 0; r < 4; r++) {
                pe[r]   = __expf(S[2*j][r]);
                pe[4+r] = __expf(S[2*j+1][r]);
            }
            lsum0 += pe[0] + pe[1] + pe[4] + pe[5];
            lsum1 += pe[2] + pe[3] + pe[6] + pe[7];

            uint32_t phi[4], plo[4];
            #pragma unroll
            for (int p = 0; p < 4; p++)
                split2(pe[2*p], pe[2*p+1], phi[p], plo[p]);

            #pragma unroll
            for (int dbp = 0; dbp < 8; dbp++) {
                uint32_t va = v_base + (uint32_t)(j << 12) + ((((uint32_t)(dbp << 5)) + v_ho) ^ v_xor);
                uint32_t vh[4], vl[4];
                LDSM4T(vh, s_vhi + va);
                MMA16816(O[2*dbp],   phi, vh[0], vh[1]);
                MMA16816(O[2*dbp+1], phi, vh[2], vh[3]);
                MMA16816(O[2*dbp],   plo, vh[0], vh[1]);
                MMA16816(O[2*dbp+1], plo, vh[2], vh[3]);
                LDSM4T(vl, s_vlo + va);
                MMA16816(O[2*dbp],   phi, vl[0], vl[1]);
                MMA16816(O[2*dbp+1], phi, vl[2], vl[3]);
            }
        }
    }

    // ---- epilogue: reduce row-sums across quad lanes, normalize, store ----
    lsum0 += __shfl_xor_sync(0xffffffffu, lsum0, 1);
    lsum0 += __shfl_xor_sync(0xffffffffu, lsum0, 2);
    lsum1 += __shfl_xor_sync(0xffffffffu, lsum1, 1);
    lsum1 += __shfl_xor_sync(0xffffffffu, lsum1, 2);
    const float inv0 = 1.0f / lsum0;
    const float inv1 = 1.0f / lsum1;

    const int g  = lane >> 2;
    const int c2 = (lane & 3) << 1;
    const size_t row0 = (size_t)b * Nn + (size_t)qt * 128 + wid*16 + g;
    const size_t row1 = row0 + 8;
    #pragma unroll
    for (int nb = 0; nb < 16; nb++) {
        float2 v0 = make_float2(O[nb][0] * inv0, O[nb][1] * inv0);
        float2 v1 = make_float2(O[nb][2] * inv1, O[nb][3] * inv1);
        *(float2*)(out + row0 * Dd + nb*8 + c2) = v0;
        *(float2*)(out + row1 * Dd + nb*8 + c2) = v1;
    }
}

// ---------------------------------------------------------------------------

extern "C" void kernel_launch(void* const* d_in, const int* in_sizes, int n_in,
                              void* d_out, int out_size)
{
    (void)in_sizes; (void)n_in; (void)out_size;
    const float* X  = (const float*)d_in[0];
    const float* Wq = (const float*)d_in[1];
    const float* Wk = (const float*)d_in[2];
    const float* Wv = (const float*)d_in[3];
    float* out = (float*)d_out;

    cudaFuncSetAttribute(proj_kernel,     cudaFuncAttributeMaxDynamicSharedMemorySize, PROJ_SMEM);
    cudaFuncSetAttribute(attn_mma_kernel, cudaFuncAttributeMaxDynamicSharedMemorySize, ATTN_SMEM);

    dim3 pgrid((Bb*Nn)/128, 3);
    proj_kernel<<<pgrid, 256, PROJ_SMEM>>>(X, Wq, Wk, Wv);

    dim3 agrid(Nn/128, Bb);
    attn_mma_kernel<<<agrid, 256, ATTN_SMEM>>>(out);
}

// round 8
// speedup vs baseline: 1.0034x; 1.0034x over previous
#include <cuda_runtime.h>
#include <cuda_bf16.h>
#include <math.h>
#include <stdint.h>

#define Bb 8
#define Nn 4096
#define Dd 128
#define TKr 64
#define KTILES (Nn/TKr)     // 64

// ---------------- device scratch (no allocs allowed) ----------------
// bf16 hi/lo row-major [B*N][128]
__device__ __align__(16) __nv_bfloat16 g_Qhi[Bb*Nn*Dd];
__device__ __align__(16) __nv_bfloat16 g_Qlo[Bb*Nn*Dd];
__device__ __align__(16) __nv_bfloat16 g_Khi[Bb*Nn*Dd];
__device__ __align__(16) __nv_bfloat16 g_Klo[Bb*Nn*Dd];
__device__ __align__(16) __nv_bfloat16 g_Vhi[Bb*Nn*Dd];
__device__ __align__(16) __nv_bfloat16 g_Vlo[Bb*Nn*Dd];

__device__ __forceinline__ uint32_t smem_u32(const void* p) {
    uint32_t a;
    asm("{ .reg .u64 t; cvta.to.shared.u64 t, %1; cvt.u32.u64 %0, t; }" : "=r"(a) : "l"(p));
    return a;
}

#define LDSM4(r, addr) \
    asm volatile("ldmatrix.sync.aligned.m8n8.x4.shared.b16 {%0,%1,%2,%3}, [%4];" \
        : "=r"((r)[0]), "=r"((r)[1]), "=r"((r)[2]), "=r"((r)[3]) : "r"(addr))
#define LDSM4T(r, addr) \
    asm volatile("ldmatrix.sync.aligned.m8n8.x4.trans.shared.b16 {%0,%1,%2,%3}, [%4];" \
        : "=r"((r)[0]), "=r"((r)[1]), "=r"((r)[2]), "=r"((r)[3]) : "r"(addr))
#define MMA16816(d, a, b0, b1) \
    asm volatile("mma.sync.aligned.m16n8k16.row.col.f32.bf16.bf16.f32 " \
        "{%0,%1,%2,%3}, {%4,%5,%6,%7}, {%8,%9}, {%0,%1,%2,%3};" \
        : "+f"((d)[0]), "+f"((d)[1]), "+f"((d)[2]), "+f"((d)[3]) \
        : "r"((a)[0]), "r"((a)[1]), "r"((a)[2]), "r"((a)[3]), "r"(b0), "r"(b1))
#define CP_ASYNC16(sdst, gsrc) \
    asm volatile("cp.async.cg.shared.global [%0], [%1], 16;" :: "r"(sdst), "l"(gsrc))
#define CP_COMMIT() asm volatile("cp.async.commit_group;" ::: "memory")
#define CP_WAIT1()  asm volatile("cp.async.wait_group 1;" ::: "memory")
#define CP_WAIT0()  asm volatile("cp.async.wait_group 0;" ::: "memory")

// hi/lo split of 2 floats -> two packed bf16x2 words
__device__ __forceinline__ void split2(float f0, float f1, uint32_t& hw, uint32_t& lw) {
    __nv_bfloat162 hh = __floats2bfloat162_rn(f0, f1);
    float r0 = f0 - __bfloat162float(hh.x);
    float r1 = f1 - __bfloat162float(hh.y);
    __nv_bfloat162 ll = __floats2bfloat162_rn(r0, r1);
    hw = *(uint32_t*)&hh;
    lw = *(uint32_t*)&ll;
}

// ---------------------------------------------------------------------------
// Tensorized projection. grid=(256, 3), block=256, smem 128KB.
// Each CTA: 128 rows of X, full 128x128 W. Y = X W^T via 3-pass bf16 hi/lo.
// Emits bf16 hi/lo row-major into g_{Q,K,V}{hi,lo}.
// ---------------------------------------------------------------------------
#define PJ_XHI 0
#define PJ_XLO 32768
#define PJ_WHI 65536
#define PJ_WLO 98304
#define PROJ_SMEM 131072

__global__ __launch_bounds__(256, 1) void proj_kernel(
    const float* __restrict__ X,
    const float* __restrict__ Wq,
    const float* __restrict__ Wk,
    const float* __restrict__ Wv)
{
    extern __shared__ char smem[];
    const uint32_t sb = smem_u32(smem);
    const int tid  = threadIdx.x;
    const int lane = tid & 31;
    const int wid  = tid >> 5;
    const int row0 = blockIdx.x * 128;

    const float* W = (blockIdx.y == 0) ? Wq : (blockIdx.y == 1) ? Wk : Wv;
    __nv_bfloat16* HI = (blockIdx.y == 0) ? g_Qhi : (blockIdx.y == 1) ? g_Khi : g_Vhi;
    __nv_bfloat16* LO = (blockIdx.y == 0) ? g_Qlo : (blockIdx.y == 1) ? g_Klo : g_Vlo;

    // load + split X tile and W into swizzled smem images (2 threads per row)
    {
        const int r = tid >> 1;
        const int h = tid & 1;
        const uint32_t rx = (uint32_t)((r & 7) << 4);
        #pragma unroll
        for (int c4 = 0; c4 < 16; c4++) {
            int col = h*64 + c4*4;
            uint32_t off = (uint32_t)(r*256) + ((((uint32_t)(col >> 3)) << 4) ^ rx) + (uint32_t)((col & 7) << 1);
            float4 v = *(const float4*)(X + (size_t)(row0 + r) * Dd + col);
            uint32_t h0, l0, h1, l1;
            split2(v.x, v.y, h0, l0);
            split2(v.z, v.w, h1, l1);
            *(uint32_t*)(smem + PJ_XHI + off)     = h0;
            *(uint32_t*)(smem + PJ_XHI + off + 4) = h1;
            *(uint32_t*)(smem + PJ_XLO + off)     = l0;
            *(uint32_t*)(smem + PJ_XLO + off + 4) = l1;
            float4 w = *(const float4*)(W + (size_t)r * Dd + col);
            split2(w.x, w.y, h0, l0);
            split2(w.z, w.w, h1, l1);
            *(uint32_t*)(smem + PJ_WHI + off)     = h0;
            *(uint32_t*)(smem + PJ_WHI + off + 4) = h1;
            *(uint32_t*)(smem + PJ_WLO + off)     = l0;
            *(uint32_t*)(smem + PJ_WLO + off + 4) = l1;
        }
    }
    __syncthreads();

    // fragment address components (same layout as attn kernel)
    const int      qrow   = wid*16 + (lane & 15);
    const uint32_t q_base = qrow*256;
    const uint32_t q_xor  = (uint32_t)((qrow & 7) << 4);
    const uint32_t q_ho   = (uint32_t)((lane >> 4) << 4);
    const int      krow   = ((lane >> 4) << 3) + (lane & 7);
    const uint32_t k_base = krow*256;
    const uint32_t k_xor  = (uint32_t)((krow & 7) << 4);
    const uint32_t k_ho   = (uint32_t)(((lane >> 3) & 1) << 4);

    float acc[16][4];
    #pragma unroll
    for (int nb = 0; nb < 16; nb++)
        #pragma unroll
        for (int r = 0; r < 4; r++) acc[nb][r] = 0.0f;

    #pragma unroll
    for (int kk = 0; kk < 8; kk++) {
        uint32_t ah[4], al[4];
        uint32_t qc = ((uint32_t)(kk << 5) + q_ho) ^ q_xor;
        LDSM4(ah, sb + PJ_XHI + q_base + qc);
        LDSM4(al, sb + PJ_XLO + q_base + qc);
        #pragma unroll
        for (int nbp = 0; nbp < 8; nbp++) {
            uint32_t ka = k_base + (uint32_t)(nbp << 12) + ((((uint32_t)(kk << 5)) + k_ho) ^ k_xor);
            uint32_t bh[4], bl[4];
            LDSM4(bh, sb + PJ_WHI + ka);
            MMA16816(acc[2*nbp],   ah, bh[0], bh[1]);
            MMA16816(acc[2*nbp+1], ah, bh[2], bh[3]);
            MMA16816(acc[2*nbp],   al, bh[0], bh[1]);
            MMA16816(acc[2*nbp+1], al, bh[2], bh[3]);
            LDSM4(bl, sb + PJ_WLO + ka);
            MMA16816(acc[2*nbp],   ah, bl[0], bl[1]);
            MMA16816(acc[2*nbp+1], ah, bl[2], bl[3]);
        }
    }

    // epilogue: split fp32 acc -> bf16 hi/lo, write row-major
    const int g  = lane >> 2;
    const int c2 = (lane & 3) << 1;
    const size_t r0 = (size_t)(row0 + wid*16 + g);
    const size_t r1 = r0 + 8;
    #pragma unroll
    for (int nb = 0; nb < 16; nb++) {
        uint32_t hw, lw;
        split2(acc[nb][0], acc[nb][1], hw, lw);
        *(uint32_t*)(HI + r0 * Dd + nb*8 + c2) = hw;
        *(uint32_t*)(LO + r0 * Dd + nb*8 + c2) = lw;
        split2(acc[nb][2], acc[nb][3], hw, lw);
        *(uint32_t*)(HI + r1 * Dd + nb*8 + c2) = hw;
        *(uint32_t*)(LO + r1 * Dd + nb*8 + c2) = lw;
    }
}

// ---------------------------------------------------------------------------
// mma.sync flash attention, cp.async double-buffered, TK=64 per stage.
// grid=(32, 8), block=256. Each warp owns 16 q-rows.
// SMEM: QHI 0..32K | QLO 32K..64K | stage0 64K..128K | stage1 128K..192K
//   within stage: KHI 0 | KLO 16K | VHI 32K | VLO 48K   (64 rows x 256B each)
// ---------------------------------------------------------------------------
#define T_QHI 0
#define T_QLO 32768
#define T_STG 65536
#define STG_STRIDE 65536
#define S_KHI 0
#define S_KLO 16384
#define S_VHI 32768
#define S_VLO 49152
#define ATTN_SMEM 196608

__global__ __launch_bounds__(256, 1) void attn_mma_kernel(float* __restrict__ out)
{
    extern __shared__ char smem[];
    const uint32_t sb = smem_u32(smem);
    const int tid  = threadIdx.x;
    const int lane = tid & 31;
    const int wid  = tid >> 5;
    const int b    = blockIdx.y;
    const int qt   = blockIdx.x;

    // ---- load Q tile (hi/lo), swizzled ----
    {
        const size_t qb = ((size_t)b * Nn + (size_t)qt * 128) * 16;
        const uint4* qh = (const uint4*)g_Qhi;
        const uint4* ql = (const uint4*)g_Qlo;
        #pragma unroll
        for (int i = 0; i < 8; i++) {
            int idx = tid + i * 256;
            int row = idx >> 4, ch = idx & 15;
            uint32_t off = row*256 + (((uint32_t)(ch << 4)) ^ ((uint32_t)((row & 7) << 4)));
            *(uint4*)(smem + T_QHI + off) = qh[qb + idx];
            *(uint4*)(smem + T_QLO + off) = ql[qb + idx];
        }
    }

    // ---- fragment address components ----
    const int      qrow   = wid*16 + (lane & 15);
    const uint32_t q_base = qrow*256;
    const uint32_t q_xor  = (uint32_t)((qrow & 7) << 4);
    const uint32_t q_ho   = (uint32_t)((lane >> 4) << 4);
    const int      krow   = ((lane >> 4) << 3) + (lane & 7);
    const uint32_t k_base = krow*256;
    const uint32_t k_xor  = (uint32_t)((krow & 7) << 4);
    const uint32_t k_ho   = (uint32_t)(((lane >> 3) & 1) << 4);
    const int      vrow   = (((lane >> 3) & 1) << 3) + (lane & 7);
    const uint32_t v_base = vrow*256;
    const uint32_t v_xor  = (uint32_t)((vrow & 7) << 4);
    const uint32_t v_ho   = (uint32_t)((lane >> 4) << 4);

    const uint32_t s_qhi = sb + T_QHI, s_qlo = sb + T_QLO;

    // per-stage prefetch: 16 cp.async per thread (4 matrices x 4 chunks)
    const __nv_bfloat16* kh_g = g_Khi;
    const __nv_bfloat16* kl_g = g_Klo;
    const __nv_bfloat16* vh_g = g_Vhi;
    const __nv_bfloat16* vl_g = g_Vlo;

    auto prefetch = [&](int kt, int stg) {
        const size_t kb = ((size_t)b * Nn + (size_t)kt * TKr) * 16;
        const uint32_t sdst = sb + T_STG + (uint32_t)stg * STG_STRIDE;
        const uint4* kh = (const uint4*)kh_g + kb;
        const uint4* kl = (const uint4*)kl_g + kb;
        const uint4* vh = (const uint4*)vh_g + kb;
        const uint4* vl = (const uint4*)vl_g + kb;
        #pragma unroll
        for (int i = 0; i < 4; i++) {
            int idx = tid + i * 256;                 // 0..1023
            int row = idx >> 4, ch = idx & 15;
            uint32_t off = row*256 + (((uint32_t)(ch << 4)) ^ ((uint32_t)((row & 7) << 4)));
            CP_ASYNC16(sdst + S_KHI + off, (const void*)(kh + idx));
            CP_ASYNC16(sdst + S_KLO + off, (const void*)(kl + idx));
            CP_ASYNC16(sdst + S_VHI + off, (const void*)(vh + idx));
            CP_ASYNC16(sdst + S_VLO + off, (const void*)(vl + idx));
        }
    };

    float O[16][4];
    #pragma unroll
    for (int nb = 0; nb < 16; nb++)
        #pragma unroll
        for (int r = 0; r < 4; r++) O[nb][r] = 0.0f;
    float lsum0 = 0.0f, lsum1 = 0.0f;

    prefetch(0, 0);
    CP_COMMIT();

    for (int kt = 0; kt < KTILES; kt++) {
        __syncthreads();   // all warps done with stage (kt+1)&1 from iteration kt-1
        if (kt + 1 < KTILES) {
            prefetch(kt + 1, (kt + 1) & 1);
            CP_COMMIT();
            CP_WAIT1();    // tile kt landed (this thread)
        } else {
            CP_WAIT0();
        }
        __syncthreads();   // tile kt landed (all threads)

        const uint32_t stg   = sb + T_STG + (uint32_t)(kt & 1) * STG_STRIDE;
        const uint32_t s_khi = stg + S_KHI, s_klo = stg + S_KLO;
        const uint32_t s_vhi = stg + S_VHI, s_vlo = stg + S_VLO;

        // ---- S = Qhi*Khi^T + Qlo*Khi^T + Qhi*Klo^T  (16 x 64) ----
        float S[8][4];
        #pragma unroll
        for (int nb = 0; nb < 8; nb++)
            #pragma unroll
            for (int r = 0; r < 4; r++) S[nb][r] = 0.0f;

        #pragma unroll
        for (int kk = 0; kk < 8; kk++) {
            uint32_t ah[4], al[4];
            uint32_t qc = ((uint32_t)(kk << 5) + q_ho) ^ q_xor;
            LDSM4(ah, s_qhi + q_base + qc);
            LDSM4(al, s_qlo + q_base + qc);
            #pragma unroll
            for (int nbp = 0; nbp < 4; nbp++) {
                uint32_t ka = k_base + (uint32_t)(nbp << 12) + ((((uint32_t)(kk << 5)) + k_ho) ^ k_xor);
                uint32_t bh[4], bl[4];
                LDSM4(bh, s_khi + ka);
                MMA16816(S[2*nbp],   ah, bh[0], bh[1]);
                MMA16816(S[2*nbp+1], ah, bh[2], bh[3]);
                MMA16816(S[2*nbp],   al, bh[0], bh[1]);
                MMA16816(S[2*nbp+1], al, bh[2], bh[3]);
                LDSM4(bl, s_klo + ka);
                MMA16816(S[2*nbp],   ah, bl[0], bl[1]);
                MMA16816(S[2*nbp+1], ah, bl[2], bl[3]);
            }
        }

        // ---- softmax (registers only) + O += Phi*V(hi+lo) + Plo*Vhi ----
        #pragma unroll
        for (int j = 0; j < 4; j++) {
            float pe[8];
            #pragma unroll
            for (int r = 0; r < 4; r++) {
                pe[r]   = __expf(S[2*j][r]);
                pe[4+r] = __expf(S[2*j+1][r]);
            }
            lsum0 += pe[0] + pe[1] + pe[4] + pe[5];
            lsum1 += pe[2] + pe[3] + pe[6] + pe[7];

            uint32_t phi[4], plo[4];
            #pragma unroll
            for (int p = 0; p < 4; p++)
                split2(pe[2*p], pe[2*p+1], phi[p], plo[p]);

            #pragma unroll
            for (int dbp = 0; dbp < 8; dbp++) {
                uint32_t va = v_base + (uint32_t)(j << 12) + ((((uint32_t)(dbp << 5)) + v_ho) ^ v_xor);
                uint32_t vh[4], vl[4];
                LDSM4T(vh, s_vhi + va);
                MMA16816(O[2*dbp],   phi, vh[0], vh[1]);
                MMA16816(O[2*dbp+1], phi, vh[2], vh[3]);
                MMA16816(O[2*dbp],   plo, vh[0], vh[1]);
                MMA16816(O[2*dbp+1], plo, vh[2], vh[3]);
                LDSM4T(vl, s_vlo + va);
                MMA16816(O[2*dbp],   phi, vl[0], vl[1]);
                MMA16816(O[2*dbp+1], phi, vl[2], vl[3]);
            }
        }
    }

    // ---- epilogue: reduce row-sums across quad lanes, normalize, store ----
    lsum0 += __shfl_xor_sync(0xffffffffu, lsum0, 1);
    lsum0 += __shfl_xor_sync(0xffffffffu, lsum0, 2);
    lsum1 += __shfl_xor_sync(0xffffffffu, lsum1, 1);
    lsum1 += __shfl_xor_sync(0xffffffffu, lsum1, 2);
    const float inv0 = 1.0f / lsum0;
    const float inv1 = 1.0f / lsum1;

    const int g  = lane >> 2;
    const int c2 = (lane & 3) << 1;
    const size_t row0 = (size_t)b * Nn + (size_t)qt * 128 + wid*16 + g;
    const size_t row1 = row0 + 8;
    #pragma unroll
    for (int nb = 0; nb < 16; nb++) {
        float2 v0 = make_float2(O[nb][0] * inv0, O[nb][1] * inv0);
        float2 v1 = make_float2(O[nb][2] * inv1, O[nb][3] * inv1);
        *(float2*)(out + row0 * Dd + nb*8 + c2) = v0;
        *(float2*)(out + row1 * Dd + nb*8 + c2) = v1;
    }
}

// ---------------------------------------------------------------------------

extern "C" void kernel_launch(void* const* d_in, const int* in_sizes, int n_in,
                              void* d_out, int out_size)
{
    (void)in_sizes; (void)n_in; (void)out_size;
    const float* X  = (const float*)d_in[0];
    const float* Wq = (const float*)d_in[1];
    const float* Wk = (const float*)d_in[2];
    const float* Wv = (const float*)d_in[3];
    float* out = (float*)d_out;

    cudaFuncSetAttribute(proj_kernel,     cudaFuncAttributeMaxDynamicSharedMemorySize, PROJ_SMEM);
    cudaFuncSetAttribute(attn_mma_kernel, cudaFuncAttributeMaxDynamicSharedMemorySize, ATTN_SMEM);

    dim3 pgrid((Bb*Nn)/128, 3);
    proj_kernel<<<pgrid, 256, PROJ_SMEM>>>(X, Wq, Wk, Wv);

    dim3 agrid(Nn/128, Bb);
    attn_mma_kernel<<<agrid, 256, ATTN_SMEM>>>(out);
}